// round 9
// baseline (speedup 1.0000x reference)
#include <cuda_runtime.h>
#include <cuda_bf16.h>
#include <cstdint>

// Problem constants
#define NUM_CLASSES 1024
#define DIM 512
#define NQ 65536
#define NS 65536

// GEMM tiling (Ampere-style mma.sync path — tcgen05 PTX is rejected by this
// toolchain's compute_103 virtual arch, so we use baseline-PTX tensor ops)
#define BM 128
#define BN 128
#define BK 64
#define STAGES 3
#define K_ITERS (DIM / BK)               // 8
#define TILE_BYTES (BM * BK * 2)         // 16384 per operand per stage
#define SMEM_B_OFF (STAGES * TILE_BYTES) // 49152
#define SMEM_TOTAL (2 * STAGES * TILE_BYTES) // 98304

// ---------------- scratch (device globals: allocation-free rule) ----------------
__device__ __align__(16) float g_proto_sums[NUM_CLASSES * DIM];   // 2 MB
__device__ float g_counts[NUM_CLASSES];
__device__ float g_psq[NUM_CLASSES];
__device__ float g_qsq[NQ];
__device__ __align__(16) __nv_bfloat16 g_zq[(size_t)NQ * DIM];        // 64 MB
__device__ __align__(16) __nv_bfloat16 g_protos[NUM_CLASSES * DIM];   // 1 MB

// ---------------- PTX helpers ----------------
__device__ __forceinline__ uint32_t smem_u32(const void* p) {
    uint32_t a;
    asm("{ .reg .u64 t; cvta.to.shared.u64 t, %1; cvt.u32.u64 %0, t; }" : "=r"(a) : "l"(p));
    return a;
}

__device__ __forceinline__ void cp16(uint32_t saddr, const void* g) {
    asm volatile("cp.async.cg.shared.global [%0], [%1], 16;"
                 :: "r"(saddr), "l"(__cvta_generic_to_global(g)) : "memory");
}
#define CP_COMMIT() asm volatile("cp.async.commit_group;" ::: "memory")
#define CP_WAIT(n)  asm volatile("cp.async.wait_group %0;" :: "n"(n) : "memory")

#define LDSM_X4(r, addr) \
    asm volatile("ldmatrix.sync.aligned.m8n8.x4.shared.b16 {%0,%1,%2,%3}, [%4];" \
                 : "=r"((r)[0]), "=r"((r)[1]), "=r"((r)[2]), "=r"((r)[3]) : "r"(addr))

__device__ __forceinline__ void mma16816(float* d, const uint32_t* a, const uint32_t* b) {
    asm volatile(
        "mma.sync.aligned.m16n8k16.row.col.f32.bf16.bf16.f32 "
        "{%0,%1,%2,%3}, {%4,%5,%6,%7}, {%8,%9}, {%0,%1,%2,%3};"
        : "+f"(d[0]), "+f"(d[1]), "+f"(d[2]), "+f"(d[3])
        : "r"(a[0]), "r"(a[1]), "r"(a[2]), "r"(a[3]), "r"(b[0]), "r"(b[1]));
}

// ---------------- prep kernels ----------------
__global__ void zero_kernel() {
    int i = blockIdx.x * blockDim.x + threadIdx.x;
    if (i < NUM_CLASSES * DIM) g_proto_sums[i] = 0.0f;
    if (i < NUM_CLASSES) g_counts[i] = 0.0f;
}

// y_support is INT32 in the harness buffer (JAX default int — the reference's
// jnp.int64 is silently downcast without x64 mode). Reading it as int64 was the
// R7/R8 bug: every row got the label of row 2r and half the rows read past the
// buffer, giving the deterministic rel_err = 2.55e-2.
__global__ void __launch_bounds__(128) accum_kernel(const float* __restrict__ zs,
                                                    const int* __restrict__ ys) {
    int r = blockIdx.x;
    int t = threadIdx.x;
    int c = ys[r];
    float4 v = reinterpret_cast<const float4*>(zs + (size_t)r * DIM)[t];
    atomicAdd(reinterpret_cast<float4*>(g_proto_sums) + c * (DIM / 4) + t, v);
    if (t == 0) atomicAdd(&g_counts[c], 1.0f);
}

__global__ void __launch_bounds__(128) finalize_kernel() {
    int c = blockIdx.x;
    int t = threadIdx.x;
    float inv = 1.0f / fmaxf(g_counts[c], 1.0f);
    float4 s = reinterpret_cast<const float4*>(g_proto_sums)[c * (DIM / 4) + t];
    float4 p = make_float4(s.x * inv, s.y * inv, s.z * inv, s.w * inv);
    __nv_bfloat162* dst = reinterpret_cast<__nv_bfloat162*>(g_protos + (size_t)c * DIM + t * 4);
    dst[0] = __floats2bfloat162_rn(p.x, p.y);
    dst[1] = __floats2bfloat162_rn(p.z, p.w);
    float sq = p.x * p.x + p.y * p.y + p.z * p.z + p.w * p.w;
    #pragma unroll
    for (int o = 16; o > 0; o >>= 1) sq += __shfl_down_sync(0xffffffffu, sq, o);
    __shared__ float ws[4];
    if ((t & 31) == 0) ws[t >> 5] = sq;
    __syncthreads();
    if (t == 0) g_psq[c] = ws[0] + ws[1] + ws[2] + ws[3];
}

__global__ void __launch_bounds__(128) qprep_kernel(const float* __restrict__ zq) {
    int n = blockIdx.x;
    int t = threadIdx.x;
    float4 q = reinterpret_cast<const float4*>(zq + (size_t)n * DIM)[t];
    __nv_bfloat162* dst = reinterpret_cast<__nv_bfloat162*>(g_zq + (size_t)n * DIM + t * 4);
    dst[0] = __floats2bfloat162_rn(q.x, q.y);
    dst[1] = __floats2bfloat162_rn(q.z, q.w);
    float sq = q.x * q.x + q.y * q.y + q.z * q.z + q.w * q.w;
    #pragma unroll
    for (int o = 16; o > 0; o >>= 1) sq += __shfl_down_sync(0xffffffffu, sq, o);
    __shared__ float ws[4];
    if ((t & 31) == 0) ws[t >> 5] = sq;
    __syncthreads();
    if (t == 0) g_qsq[n] = ws[0] + ws[1] + ws[2] + ws[3];
}

// ---------------- GEMM stage loader ----------------
// Tile layout in SMEM: 128 rows x 64 bf16 (128 B/row), XOR swizzle:
// 16B-chunk index ^= (row & 7)  -> conflict-free for cp.async stores + ldmatrix reads.
__device__ __forceinline__ void load_stage(uint32_t sbase, int stage, int kit,
                                           int m_base, int n_base, int tid) {
    int k0 = kit * BK;
    uint32_t sA = sbase + stage * TILE_BYTES;
    uint32_t sB = sbase + SMEM_B_OFF + stage * TILE_BYTES;
    #pragma unroll
    for (int i = 0; i < 4; i++) {
        int j = tid + i * 256;               // 0..1023 16B chunks
        int row = j >> 3;
        int ch = j & 7;
        uint32_t soff = (uint32_t)row * 128u + (uint32_t)((ch ^ (row & 7)) << 4);
        cp16(sA + soff, g_zq + (size_t)(m_base + row) * DIM + k0 + ch * 8);
        cp16(sB + soff, g_protos + (size_t)(n_base + row) * DIM + k0 + ch * 8);
    }
}

// ---------------- main GEMM + fused epilogue ----------------
// 8 warps: 4 (M) x 2 (N). Warp tile 32 x 64. logits = 2*cross - q_sq - p_sq.
__global__ void __launch_bounds__(256, 2) gemm_kernel(float* __restrict__ out) {
    extern __shared__ char smem[];
    uint32_t sbase = smem_u32(smem);
    int tid = threadIdx.x;
    int lane = tid & 31;
    int wid = tid >> 5;
    int warp_m = (wid & 3) * 32;
    int warp_n = (wid >> 2) * 64;
    int n_base = blockIdx.x * BN;    // x fast -> 8 CTAs share each A tile in L2
    int m_base = blockIdx.y * BM;

    float d[2][8][4];
    #pragma unroll
    for (int mt = 0; mt < 2; mt++)
        #pragma unroll
        for (int nt = 0; nt < 8; nt++)
            #pragma unroll
            for (int i = 0; i < 4; i++) d[mt][nt][i] = 0.0f;

    // ldmatrix per-lane within-tile offsets
    // A (x4): lanes 0-15 -> rows m..m+15 @ k-chunk base, lanes 16-31 -> same rows @ +8 elems
    int a_r = warp_m + (lane & 15);
    uint32_t aoff0 = (uint32_t)a_r * 128u;
    uint32_t aoff1 = aoff0 + 16u * 128u;
    int ax = a_r & 7;                  // (a_r+16) & 7 == ax
    int a_cadd = lane >> 4;            // 0/1
    // B (x4): two n8 tiles per call; rows n + (lane>>4)*8 + (lane&7), chunk + ((lane>>3)&1)
    int b_r = warp_n + ((lane >> 4) << 3) + (lane & 7);
    uint32_t boff = (uint32_t)b_r * 128u;
    int bx = b_r & 7;                  // +16 rows keeps bx
    int b_cadd = (lane >> 3) & 1;

    // prologue: stages 0,1
    load_stage(sbase, 0, 0, m_base, n_base, tid); CP_COMMIT();
    load_stage(sbase, 1, 1, m_base, n_base, tid); CP_COMMIT();

    int stage = 0;
    for (int kit = 0; kit < K_ITERS; kit++) {
        // Tail-safe wait: on the last iteration drain everything (empty trailing
        // groups make wait_group 1 sufficient, but wait 0 is belt-and-braces).
        if (kit == K_ITERS - 1) CP_WAIT(0); else CP_WAIT(1);
        __syncthreads();         // all compute on the buffer we are about to refill is done
        if (kit + STAGES - 1 < K_ITERS)
            load_stage(sbase, (stage + STAGES - 1) % STAGES, kit + STAGES - 1,
                       m_base, n_base, tid);
        CP_COMMIT();             // unconditional: empty groups keep group counts consistent

        uint32_t sA = sbase + stage * TILE_BYTES;
        uint32_t sB = sbase + SMEM_B_OFF + stage * TILE_BYTES;
        #pragma unroll
        for (int ks = 0; ks < 4; ks++) {           // 4 x k16 per BK=64
            uint32_t a0[4], a1[4];
            uint32_t ca = (uint32_t)(ks * 2 + a_cadd);
            LDSM_X4(a0, sA + aoff0 + ((ca ^ (uint32_t)ax) << 4));
            LDSM_X4(a1, sA + aoff1 + ((ca ^ (uint32_t)ax) << 4));
            uint32_t b[4][4];
            uint32_t cb = (uint32_t)(ks * 2 + b_cadd);
            #pragma unroll
            for (int g = 0; g < 4; g++)
                LDSM_X4(b[g], sB + boff + (uint32_t)g * 2048u + ((cb ^ (uint32_t)bx) << 4));
            #pragma unroll
            for (int nt = 0; nt < 8; nt++) {
                mma16816(d[0][nt], a0, &b[nt >> 1][(nt & 1) * 2]);
                mma16816(d[1][nt], a1, &b[nt >> 1][(nt & 1) * 2]);
            }
        }
        stage++; if (stage == STAGES) stage = 0;
    }

    // Epilogue: c frag lane map (m16n8): rows lane/4 and lane/4+8, cols (lane%4)*2, +1
    #pragma unroll
    for (int mt = 0; mt < 2; mt++) {
        int m0 = m_base + warp_m + mt * 16 + (lane >> 2);
        int m1 = m0 + 8;
        float q0 = g_qsq[m0];
        float q1 = g_qsq[m1];
        float* r0 = out + (size_t)m0 * NUM_CLASSES + n_base + warp_n;
        float* r1 = out + (size_t)m1 * NUM_CLASSES + n_base + warp_n;
        #pragma unroll
        for (int nt = 0; nt < 8; nt++) {
            int c = nt * 8 + (lane & 3) * 2;
            float p0 = g_psq[n_base + warp_n + c];
            float p1 = g_psq[n_base + warp_n + c + 1];
            float2 v0, v1;
            v0.x = 2.0f * d[mt][nt][0] - q0 - p0;
            v0.y = 2.0f * d[mt][nt][1] - q0 - p1;
            v1.x = 2.0f * d[mt][nt][2] - q1 - p0;
            v1.y = 2.0f * d[mt][nt][3] - q1 - p1;
            *reinterpret_cast<float2*>(r0 + c) = v0;
            *reinterpret_cast<float2*>(r1 + c) = v1;
        }
    }
}

// ---------------- launch ----------------
extern "C" void kernel_launch(void* const* d_in, const int* in_sizes, int n_in,
                              void* d_out, int out_size) {
    const float* zs = (const float*)d_in[0];   // z_support [65536, 512] f32
    const int* ys = (const int*)d_in[1];       // y_support [65536] int32 (JAX default int!)
    const float* zq = (const float*)d_in[2];   // z_query  [65536, 512] f32
    float* out = (float*)d_out;                // [65536, 1024] f32

    zero_kernel<<<(NUM_CLASSES * DIM + 255) / 256, 256>>>();
    accum_kernel<<<NS, 128>>>(zs, ys);
    finalize_kernel<<<NUM_CLASSES, 128>>>();
    qprep_kernel<<<NQ, 128>>>(zq);

    cudaFuncSetAttribute(gemm_kernel, cudaFuncAttributeMaxDynamicSharedMemorySize, SMEM_TOTAL);
    dim3 grid(NUM_CLASSES / BN, NQ / BM);  // (8, 512)
    gemm_kernel<<<grid, 256, SMEM_TOTAL>>>(out);
}

// round 12
// speedup vs baseline: 1.0786x; 1.0786x over previous
#include <cuda_runtime.h>
#include <cuda_bf16.h>
#include <cstdint>

// Problem constants
#define NUM_CLASSES 1024
#define DIM 512
#define NQ 65536
#define NS 65536

// GEMM tiling (Ampere-style mma.sync path — tcgen05 PTX is rejected by this
// toolchain's compute_103 virtual arch, so we use baseline-PTX tensor ops)
#define BM 128
#define BN 128
#define BK 64
#define STAGES 3
#define K_ITERS (DIM / BK)               // 8
#define TILE_BYTES (BM * BK * 2)         // 16384 per operand per stage
#define SMEM_B_OFF (STAGES * TILE_BYTES) // 49152
#define SMEM_TOTAL (2 * STAGES * TILE_BYTES) // 98304

// ---------------- scratch (device globals: allocation-free rule) ----------------
__device__ __align__(16) float g_proto_sums[NUM_CLASSES * DIM];   // 2 MB
__device__ float g_counts[NUM_CLASSES];
__device__ float g_psq[NUM_CLASSES];
__device__ float g_qsq[NQ];
__device__ __align__(16) __nv_bfloat16 g_zq[(size_t)NQ * DIM];        // 64 MB
__device__ __align__(16) __nv_bfloat16 g_protos[NUM_CLASSES * DIM];   // 1 MB

// ---------------- PTX helpers ----------------
__device__ __forceinline__ uint32_t smem_u32(const void* p) {
    uint32_t a;
    asm("{ .reg .u64 t; cvta.to.shared.u64 t, %1; cvt.u32.u64 %0, t; }" : "=r"(a) : "l"(p));
    return a;
}

__device__ __forceinline__ void cp16(uint32_t saddr, const void* g) {
    asm volatile("cp.async.cg.shared.global [%0], [%1], 16;"
                 :: "r"(saddr), "l"(__cvta_generic_to_global(g)) : "memory");
}
#define CP_COMMIT() asm volatile("cp.async.commit_group;" ::: "memory")
#define CP_WAIT(n)  asm volatile("cp.async.wait_group %0;" :: "n"(n) : "memory")

#define LDSM_X4(r, addr) \
    asm volatile("ldmatrix.sync.aligned.m8n8.x4.shared.b16 {%0,%1,%2,%3}, [%4];" \
                 : "=r"((r)[0]), "=r"((r)[1]), "=r"((r)[2]), "=r"((r)[3]) : "r"(addr))

__device__ __forceinline__ void mma16816(float* d, const uint32_t* a, const uint32_t* b) {
    asm volatile(
        "mma.sync.aligned.m16n8k16.row.col.f32.bf16.bf16.f32 "
        "{%0,%1,%2,%3}, {%4,%5,%6,%7}, {%8,%9}, {%0,%1,%2,%3};"
        : "+f"(d[0]), "+f"(d[1]), "+f"(d[2]), "+f"(d[3])
        : "r"(a[0]), "r"(a[1]), "r"(a[2]), "r"(a[3]), "r"(b[0]), "r"(b[1]));
}

// ---------------- prep kernels ----------------
__global__ void zero_kernel() {
    int i = blockIdx.x * blockDim.x + threadIdx.x;
    if (i < NUM_CLASSES * DIM) g_proto_sums[i] = 0.0f;
    if (i < NUM_CLASSES) g_counts[i] = 0.0f;
}

// Fused prep: replaces the serial accum_kernel + qprep_kernel pair.
// One warp per task; even global-warp -> accum(support row), odd -> qprep(query row).
// Interleaving mixes pure-streaming loads with L2-resident atomics across the whole
// chip (better DRAM + LTS utilization than running the two phases back-to-back),
// and each lane issues 4 independent float4 loads (MLP=4 vs 1 before).
// NOTE: y_support is INT32 in the harness buffer (JAX default int; the reference's
// jnp.int64 is silently downcast) — reading int64 was the R7/R8 bug.
__global__ void __launch_bounds__(256) fused_prep(const float* __restrict__ zs,
                                                  const int* __restrict__ ys,
                                                  const float* __restrict__ zq) {
    int gw = (int)((blockIdx.x * blockDim.x + threadIdx.x) >> 5);  // global warp id
    int lane = threadIdx.x & 31;
    int row = gw >> 1;
    bool is_q = (gw & 1) != 0;

    const float4* s4 = reinterpret_cast<const float4*>((is_q ? zq : zs) + (size_t)row * DIM);
    float4 v[4];
    #pragma unroll
    for (int i = 0; i < 4; i++) v[i] = s4[lane + 32 * i];   // cols 4*lane + 128*i .. +3

    if (is_q) {
        float sq = 0.0f;
        #pragma unroll
        for (int i = 0; i < 4; i++) {
            sq += v[i].x * v[i].x + v[i].y * v[i].y + v[i].z * v[i].z + v[i].w * v[i].w;
            __nv_bfloat162 a = __floats2bfloat162_rn(v[i].x, v[i].y);
            __nv_bfloat162 b = __floats2bfloat162_rn(v[i].z, v[i].w);
            uint2 u;
            u.x = *reinterpret_cast<uint32_t*>(&a);
            u.y = *reinterpret_cast<uint32_t*>(&b);
            *reinterpret_cast<uint2*>(g_zq + (size_t)row * DIM + 4 * lane + 128 * i) = u;
        }
        #pragma unroll
        for (int o = 16; o > 0; o >>= 1) sq += __shfl_down_sync(0xffffffffu, sq, o);
        if (lane == 0) g_qsq[row] = sq;
    } else {
        int c = __ldg(ys + row);
        float4* dst = reinterpret_cast<float4*>(g_proto_sums) + c * (DIM / 4);
        #pragma unroll
        for (int i = 0; i < 4; i++) atomicAdd(dst + lane + 32 * i, v[i]);
        if (lane == 0) atomicAdd(&g_counts[c], 1.0f);
    }
}

__global__ void __launch_bounds__(128) finalize_kernel() {
    int c = blockIdx.x;
    int t = threadIdx.x;
    float inv = 1.0f / fmaxf(g_counts[c], 1.0f);
    float4 s = reinterpret_cast<const float4*>(g_proto_sums)[c * (DIM / 4) + t];
    float4 p = make_float4(s.x * inv, s.y * inv, s.z * inv, s.w * inv);
    __nv_bfloat162* dst = reinterpret_cast<__nv_bfloat162*>(g_protos + (size_t)c * DIM + t * 4);
    dst[0] = __floats2bfloat162_rn(p.x, p.y);
    dst[1] = __floats2bfloat162_rn(p.z, p.w);
    float sq = p.x * p.x + p.y * p.y + p.z * p.z + p.w * p.w;
    #pragma unroll
    for (int o = 16; o > 0; o >>= 1) sq += __shfl_down_sync(0xffffffffu, sq, o);
    __shared__ float ws[4];
    if ((t & 31) == 0) ws[t >> 5] = sq;
    __syncthreads();
    if (t == 0) g_psq[c] = ws[0] + ws[1] + ws[2] + ws[3];
}

// ---------------- GEMM stage loader ----------------
// Tile layout in SMEM: 128 rows x 64 bf16 (128 B/row), XOR swizzle:
// 16B-chunk index ^= (row & 7)  -> conflict-free for cp.async stores + ldmatrix reads.
__device__ __forceinline__ void load_stage(uint32_t sbase, int stage, int kit,
                                           int m_base, int n_base, int tid) {
    int k0 = kit * BK;
    uint32_t sA = sbase + stage * TILE_BYTES;
    uint32_t sB = sbase + SMEM_B_OFF + stage * TILE_BYTES;
    #pragma unroll
    for (int i = 0; i < 4; i++) {
        int j = tid + i * 256;               // 0..1023 16B chunks
        int row = j >> 3;
        int ch = j & 7;
        uint32_t soff = (uint32_t)row * 128u + (uint32_t)((ch ^ (row & 7)) << 4);
        cp16(sA + soff, g_zq + (size_t)(m_base + row) * DIM + k0 + ch * 8);
        cp16(sB + soff, g_protos + (size_t)(n_base + row) * DIM + k0 + ch * 8);
    }
}

// ---------------- main GEMM + fused epilogue ----------------
// 8 warps: 4 (M) x 2 (N). Warp tile 32 x 64. logits = 2*cross - q_sq - p_sq.
__global__ void __launch_bounds__(256, 2) gemm_kernel(float* __restrict__ out) {
    extern __shared__ char smem[];
    uint32_t sbase = smem_u32(smem);
    int tid = threadIdx.x;
    int lane = tid & 31;
    int wid = tid >> 5;
    int warp_m = (wid & 3) * 32;
    int warp_n = (wid >> 2) * 64;
    int n_base = blockIdx.x * BN;    // x fast -> 8 CTAs share each A tile in L2
    int m_base = blockIdx.y * BM;

    float d[2][8][4];
    #pragma unroll
    for (int mt = 0; mt < 2; mt++)
        #pragma unroll
        for (int nt = 0; nt < 8; nt++)
            #pragma unroll
            for (int i = 0; i < 4; i++) d[mt][nt][i] = 0.0f;

    // ldmatrix per-lane within-tile offsets
    // A (x4): lanes 0-15 -> rows m..m+15 @ k-chunk base, lanes 16-31 -> same rows @ +8 elems
    int a_r = warp_m + (lane & 15);
    uint32_t aoff0 = (uint32_t)a_r * 128u;
    uint32_t aoff1 = aoff0 + 16u * 128u;
    int ax = a_r & 7;                  // (a_r+16) & 7 == ax
    int a_cadd = lane >> 4;            // 0/1
    // B (x4): two n8 tiles per call; rows n + (lane>>4)*8 + (lane&7), chunk + ((lane>>3)&1)
    int b_r = warp_n + ((lane >> 4) << 3) + (lane & 7);
    uint32_t boff = (uint32_t)b_r * 128u;
    int bx = b_r & 7;                  // +16 rows keeps bx
    int b_cadd = (lane >> 3) & 1;

    // prologue: stages 0,1
    load_stage(sbase, 0, 0, m_base, n_base, tid); CP_COMMIT();
    load_stage(sbase, 1, 1, m_base, n_base, tid); CP_COMMIT();

    int stage = 0;
    for (int kit = 0; kit < K_ITERS; kit++) {
        // Tail-safe wait: on the last iteration drain everything (empty trailing
        // groups make wait_group 1 sufficient, but wait 0 is belt-and-braces).
        if (kit == K_ITERS - 1) CP_WAIT(0); else CP_WAIT(1);
        __syncthreads();         // all compute on the buffer we are about to refill is done
        if (kit + STAGES - 1 < K_ITERS)
            load_stage(sbase, (stage + STAGES - 1) % STAGES, kit + STAGES - 1,
                       m_base, n_base, tid);
        CP_COMMIT();             // unconditional: empty groups keep group counts consistent

        uint32_t sA = sbase + stage * TILE_BYTES;
        uint32_t sB = sbase + SMEM_B_OFF + stage * TILE_BYTES;
        #pragma unroll
        for (int ks = 0; ks < 4; ks++) {           // 4 x k16 per BK=64
            uint32_t a0[4], a1[4];
            uint32_t ca = (uint32_t)(ks * 2 + a_cadd);
            LDSM_X4(a0, sA + aoff0 + ((ca ^ (uint32_t)ax) << 4));
            LDSM_X4(a1, sA + aoff1 + ((ca ^ (uint32_t)ax) << 4));
            uint32_t b[4][4];
            uint32_t cb = (uint32_t)(ks * 2 + b_cadd);
            #pragma unroll
            for (int g = 0; g < 4; g++)
                LDSM_X4(b[g], sB + boff + (uint32_t)g * 2048u + ((cb ^ (uint32_t)bx) << 4));
            #pragma unroll
            for (int nt = 0; nt < 8; nt++) {
                mma16816(d[0][nt], a0, &b[nt >> 1][(nt & 1) * 2]);
                mma16816(d[1][nt], a1, &b[nt >> 1][(nt & 1) * 2]);
            }
        }
        stage++; if (stage == STAGES) stage = 0;
    }

    // Epilogue: c frag lane map (m16n8): rows lane/4 and lane/4+8, cols (lane%4)*2, +1
    #pragma unroll
    for (int mt = 0; mt < 2; mt++) {
        int m0 = m_base + warp_m + mt * 16 + (lane >> 2);
        int m1 = m0 + 8;
        float q0 = g_qsq[m0];
        float q1 = g_qsq[m1];
        float* r0 = out + (size_t)m0 * NUM_CLASSES + n_base + warp_n;
        float* r1 = out + (size_t)m1 * NUM_CLASSES + n_base + warp_n;
        #pragma unroll
        for (int nt = 0; nt < 8; nt++) {
            int c = nt * 8 + (lane & 3) * 2;
            float p0 = g_psq[n_base + warp_n + c];
            float p1 = g_psq[n_base + warp_n + c + 1];
            float2 v0, v1;
            v0.x = 2.0f * d[mt][nt][0] - q0 - p0;
            v0.y = 2.0f * d[mt][nt][1] - q0 - p1;
            v1.x = 2.0f * d[mt][nt][2] - q1 - p0;
            v1.y = 2.0f * d[mt][nt][3] - q1 - p1;
            *reinterpret_cast<float2*>(r0 + c) = v0;
            *reinterpret_cast<float2*>(r1 + c) = v1;
        }
    }
}

// ---------------- launch ----------------
extern "C" void kernel_launch(void* const* d_in, const int* in_sizes, int n_in,
                              void* d_out, int out_size) {
    const float* zs = (const float*)d_in[0];   // z_support [65536, 512] f32
    const int* ys = (const int*)d_in[1];       // y_support [65536] int32 (JAX default int!)
    const float* zq = (const float*)d_in[2];   // z_query  [65536, 512] f32
    float* out = (float*)d_out;                // [65536, 1024] f32

    zero_kernel<<<(NUM_CLASSES * DIM + 255) / 256, 256>>>();
    // (NS + NQ) warp-tasks, 8 warps per 256-thread block
    fused_prep<<<(NS + NQ) / 8, 256>>>(zs, ys, zq);
    finalize_kernel<<<NUM_CLASSES, 128>>>();

    cudaFuncSetAttribute(gemm_kernel, cudaFuncAttributeMaxDynamicSharedMemorySize, SMEM_TOTAL);
    dim3 grid(NUM_CLASSES / BN, NQ / BM);  // (8, 512)
    gemm_kernel<<<grid, 256, SMEM_TOTAL>>>(out);
}